// round 16
// baseline (speedup 1.0000x reference)
#include <cuda_runtime.h>
#include <cuda_bf16.h>
#include <cstdint>
#include <math.h>

// Problem constants (fixed by setup_inputs: S=2048, U=10, D=256)
#define B_TOT 20480
#define D_DIM 256
#define S_CLS 2048
#define U_UTT 10
#define EPSF  1e-8f
#define LOG2E 1.4426950408889634f

// Scratch (static __device__ arrays: allocation-free per harness rules)
__device__ __nv_bfloat16 g_Enh[(size_t)B_TOT * D_DIM];  // normalized embeddings bf16
__device__ __nv_bfloat16 g_Cnh[(size_t)S_CLS * D_DIM];  // normalized centroids bf16 (x log2e)
__device__ float g_rowsum[B_TOT];                       // sum_k exp(sim[row,k])
__device__ float g_pos[B_TOT];                          // sim[row, label(row)]

// ===========================================================================
// helpers
// ===========================================================================
__device__ __forceinline__ uint32_t smem_to_u32(const void* p) {
    uint32_t a;
    asm("{ .reg .u64 t; cvta.to.shared.u64 t, %1; cvt.u32.u64 %0, t; }"
        : "=r"(a) : "l"(p));
    return a;
}
__device__ __forceinline__ void cp16(uint32_t dst, const void* src) {
    asm volatile("cp.async.cg.shared.global [%0], [%1], 16;"
                 :: "r"(dst), "l"(src) : "memory");
}
__device__ __forceinline__ float warpSum(float v) {
    #pragma unroll
    for (int o = 16; o; o >>= 1) v += __shfl_xor_sync(0xffffffffu, v, o);
    return v;
}
__device__ __forceinline__ float dot4(float4 a, float4 b) {
    return a.x*b.x + a.y*b.y + a.z*b.z + a.w*b.w;
}
__device__ __forceinline__ uint32_t pack_bf16x2(float lo, float hi) {
    __nv_bfloat162 p = __float22bfloat162_rn(make_float2(lo, hi));
    return *reinterpret_cast<uint32_t*>(&p);
}
__device__ __forceinline__ float ex2f(float x) {
    float r;
    asm("ex2.approx.ftz.f32 %0, %1;" : "=f"(r) : "f"(x));
    return r;
}

// ---------------------------------------------------------------------------
// Kernel 1 (fused pre-pass): block per speaker, 320 threads = 10 warps.
// (byte-identical to R15)
// ---------------------------------------------------------------------------
__global__ __launch_bounds__(320)
void pre_kernel(const float* __restrict__ emb, float* __restrict__ out) {
    __shared__ __align__(16) float rowS[U_UTT][D_DIM];
    __shared__ __align__(16) float cnS[D_DIM];
    __shared__ float red[U_UTT];
    const int s    = blockIdx.x;
    const int u    = threadIdx.x >> 5;
    const int lane = threadIdx.x & 31;
    const int t    = threadIdx.x;
    if (s == 0 && t == 0) out[0] = 0.0f;
    if (t < U_UTT) g_rowsum[s * U_UTT + t] = 0.0f;

    const float4* pr = (const float4*)(emb + ((size_t)s * U_UTT + u) * D_DIM);
    float4 a = pr[lane], b = pr[lane + 32];
    ((float4*)rowS[u])[lane]      = a;
    ((float4*)rowS[u])[lane + 32] = b;

    float sqr = warpSum(dot4(a, a) + dot4(b, b));
    float sc = 1.0f / fmaxf(sqrtf(sqr), EPSF);
    a.x *= sc; a.y *= sc; a.z *= sc; a.w *= sc;
    b.x *= sc; b.y *= sc; b.z *= sc; b.w *= sc;
    const size_t row = (size_t)s * U_UTT + u;
    uint2* outh = (uint2*)(g_Enh + row * D_DIM);
    outh[lane]      = make_uint2(pack_bf16x2(a.x, a.y), pack_bf16x2(a.z, a.w));
    outh[lane + 32] = make_uint2(pack_bf16x2(b.x, b.y), pack_bf16x2(b.z, b.w));
    __syncthreads();                       // (1) rowS complete

    float c = 0.0f;
    if (t < D_DIM) {
        #pragma unroll
        for (int uu = 0; uu < U_UTT; uu++) c += rowS[uu][t];
        c *= (1.0f / U_UTT);
    }
    float sq = warpSum(c * c);
    if (lane == 0) red[u] = sq;
    __syncthreads();                       // (2) red complete

    float tot = 0.0f;
    #pragma unroll
    for (int i = 0; i < U_UTT; i++) tot += red[i];
    const float cnorm = fmaxf(sqrtf(tot), EPSF);
    if (t < D_DIM) {
        float cn = c / cnorm;
        cnS[t] = cn;
        g_Cnh[(size_t)s * D_DIM + t] = __float2bfloat16(cn * LOG2E);
    }
    __syncthreads();                       // (3) cnS complete

    const float4* pc = (const float4*)cnS;
    float v = dot4(a, pc[lane]) + dot4(b, pc[lane + 32]);
    v = warpSum(v);
    if (lane == 0) g_pos[row] = v;
}

// ---------------------------------------------------------------------------
// Kernel 2: bf16 mma.sync GEMM (proven R12/R15 config) + PDL grid-dependency
// sync before the first global read.
// ---------------------------------------------------------------------------
#define GEMM_SMEM 65536

__global__ __launch_bounds__(256, 2)
void gemm_bf16_kernel() {
    extern __shared__ char smem[];
    const uint32_t sb = smem_to_u32(smem);
    const int tid  = threadIdx.x;
    const int lane = tid & 31;
    const int wid  = tid >> 5;
    const int rowTile = blockIdx.x * 128;
    const int colTile = blockIdx.y * 128;
    const int rowBase = (wid >> 2) * 64;   // warp row  (0 or 64)
    const int colBase = (wid & 3) * 32;    // warp col  (0,32,64,96)

    const int lrow = tid >> 3;   // 0..31 ; rows lrow + 32*j
    const int lseg = tid & 7;    // 16B segment within 128B row

    float acc[4][4][4];
    #pragma unroll
    for (int mi = 0; mi < 4; mi++)
        #pragma unroll
        for (int ni = 0; ni < 4; ni++)
            #pragma unroll
            for (int q = 0; q < 4; q++) acc[mi][ni][q] = 0.0f;

    auto load_chunk = [&](int c, int buf) {
        #pragma unroll
        for (int j = 0; j < 4; j++) {
            int row = lrow + 32 * j;
            uint32_t dst = sb + buf * 32768 + row * 128
                         + ((lseg * 16) ^ ((row & 7) << 4));
            cp16(dst,
                 g_Enh + (size_t)(rowTile + row) * D_DIM + c * 64 + lseg * 8);
            cp16(dst + 16384,
                 g_Cnh + (size_t)(colTile + row) * D_DIM + c * 64 + lseg * 8);
        }
        asm volatile("cp.async.commit_group;" ::: "memory");
    };

    // PDL: wait for pre_kernel's full completion (all writes visible) before
    // the first global read; prologue above already executed during overlap.
    cudaGridDependencySynchronize();

    load_chunk(0, 0);
    load_chunk(1, 1);

    #pragma unroll
    for (int c = 0; c < 4; c++) {
        const int buf = c & 1;
        if (c < 3) asm volatile("cp.async.wait_group 1;" ::: "memory");
        else       asm volatile("cp.async.wait_group 0;" ::: "memory");
        __syncthreads();

        const uint32_t aB = sb + buf * 32768;
        const uint32_t bB = aB + 16384;

        #pragma unroll
        for (int ks = 0; ks < 4; ks++) {
            uint32_t a[4][4];
            uint32_t b[4][2];
            #pragma unroll
            for (int mi = 0; mi < 4; mi++) {
                int r = rowBase + mi * 16 + (lane & 15);
                uint32_t addr = aB + r * 128
                    + ((ks * 32 + (lane >> 4) * 16) ^ ((r & 7) << 4));
                asm volatile(
                    "ldmatrix.sync.aligned.m8n8.x4.shared.b16 {%0,%1,%2,%3}, [%4];"
                    : "=r"(a[mi][0]), "=r"(a[mi][1]), "=r"(a[mi][2]), "=r"(a[mi][3])
                    : "r"(addr));
            }
            #pragma unroll
            for (int nn = 0; nn < 2; nn++) {
                int g = lane >> 3;                 // matrix index 0..3
                int r = colBase + (nn * 2 + (g >> 1)) * 8 + (lane & 7);
                uint32_t addr = bB + r * 128
                    + ((ks * 32 + (g & 1) * 16) ^ ((r & 7) << 4));
                asm volatile(
                    "ldmatrix.sync.aligned.m8n8.x4.shared.b16 {%0,%1,%2,%3}, [%4];"
                    : "=r"(b[nn*2][0]), "=r"(b[nn*2][1]),
                      "=r"(b[nn*2+1][0]), "=r"(b[nn*2+1][1])
                    : "r"(addr));
            }
            #pragma unroll
            for (int mi = 0; mi < 4; mi++)
                #pragma unroll
                for (int ni = 0; ni < 4; ni++) {
                    asm volatile(
                        "mma.sync.aligned.m16n8k16.row.col.f32.bf16.bf16.f32 "
                        "{%0,%1,%2,%3}, {%4,%5,%6,%7}, {%8,%9}, {%0,%1,%2,%3};"
                        : "+f"(acc[mi][ni][0]), "+f"(acc[mi][ni][1]),
                          "+f"(acc[mi][ni][2]), "+f"(acc[mi][ni][3])
                        : "r"(a[mi][0]), "r"(a[mi][1]), "r"(a[mi][2]), "r"(a[mi][3]),
                          "r"(b[ni][0]), "r"(b[ni][1]));
                }
        }
        __syncthreads();
        if (c + 2 < 4) load_chunk(c + 2, buf);
    }

    // epilogue: acc holds sim*log2e -> bare ex2 + quad-reduce + atomicAdd
    const int g  = lane >> 2;
    const int tg = lane & 3;
    #pragma unroll
    for (int mi = 0; mi < 4; mi++) {
        float s0 = 0.0f, s1 = 0.0f;
        #pragma unroll
        for (int ni = 0; ni < 4; ni++) {
            s0 += ex2f(acc[mi][ni][0]) + ex2f(acc[mi][ni][1]);
            s1 += ex2f(acc[mi][ni][2]) + ex2f(acc[mi][ni][3]);
        }
        s0 += __shfl_xor_sync(0xffffffffu, s0, 1);
        s0 += __shfl_xor_sync(0xffffffffu, s0, 2);
        s1 += __shfl_xor_sync(0xffffffffu, s1, 1);
        s1 += __shfl_xor_sync(0xffffffffu, s1, 2);
        if (tg == 0) {
            int r = rowTile + rowBase + mi * 16 + g;
            atomicAdd(&g_rowsum[r],     s0);
            atomicAdd(&g_rowsum[r + 8], s1);
        }
    }
}

// ---------------------------------------------------------------------------
// Kernel 3: loss partials -> atomicAdd into out[0]. PDL-synced on the GEMM.
// ---------------------------------------------------------------------------
__global__ void loss_kernel(float* __restrict__ out) {
    cudaGridDependencySynchronize();   // wait for gemm completion (rowsums)
    int i = blockIdx.x * 256 + threadIdx.x;
    float p = g_pos[i];
    float acc = __logf(g_rowsum[i] - __expf(p)) - p;
    __shared__ float sh[8];
    int lane = threadIdx.x & 31, w = threadIdx.x >> 5;
    acc = warpSum(acc);
    if (lane == 0) sh[w] = acc;
    __syncthreads();
    if (w == 0) {
        acc = (lane < 8) ? sh[lane] : 0.0f;
        #pragma unroll
        for (int o = 4; o; o >>= 1) acc += __shfl_xor_sync(0xffffffffu, acc, o);
        if (lane == 0) atomicAdd(out, acc * (1.0f / B_TOT));
    }
}

// ---------------------------------------------------------------------------
extern "C" void kernel_launch(void* const* d_in, const int* in_sizes, int n_in,
                              void* d_out, int out_size) {
    const float* emb = (const float*)d_in[0];
    float* out = (float*)d_out;

    cudaFuncSetAttribute(gemm_bf16_kernel,
                         cudaFuncAttributeMaxDynamicSharedMemorySize,
                         GEMM_SMEM);

    pre_kernel<<<S_CLS, 320>>>(emb, out);

    // GEMM with programmatic dependent launch (overlaps pre's tail drain)
    {
        cudaLaunchConfig_t cfg = {};
        cfg.gridDim  = dim3(B_TOT / 128, S_CLS / 128, 1);
        cfg.blockDim = dim3(256, 1, 1);
        cfg.dynamicSmemBytes = GEMM_SMEM;
        cfg.stream = 0;
        cudaLaunchAttribute attr[1];
        attr[0].id = cudaLaunchAttributeProgrammaticStreamSerialization;
        attr[0].val.programmaticStreamSerializationAllowed = 1;
        cfg.attrs = attr;
        cfg.numAttrs = 1;
        cudaLaunchKernelEx(&cfg, gemm_bf16_kernel);
    }

    // loss with programmatic dependent launch (overlaps gemm's tail drain)
    {
        cudaLaunchConfig_t cfg = {};
        cfg.gridDim  = dim3(B_TOT / 256, 1, 1);
        cfg.blockDim = dim3(256, 1, 1);
        cfg.dynamicSmemBytes = 0;
        cfg.stream = 0;
        cudaLaunchAttribute attr[1];
        attr[0].id = cudaLaunchAttributeProgrammaticStreamSerialization;
        attr[0].val.programmaticStreamSerializationAllowed = 1;
        cfg.attrs = attr;
        cfg.numAttrs = 1;
        cudaLaunchKernelEx(&cfg, loss_kernel, out);
    }
}

// round 17
// speedup vs baseline: 1.0550x; 1.0550x over previous
#include <cuda_runtime.h>
#include <cuda_bf16.h>
#include <cstdint>
#include <math.h>

// Problem constants (fixed by setup_inputs: S=2048, U=10, D=256)
#define B_TOT 20480
#define D_DIM 256
#define S_CLS 2048
#define U_UTT 10
#define EPSF  1e-8f
#define LOG2E 1.4426950408889634f

// Scratch (static __device__ arrays: allocation-free per harness rules)
__device__ __nv_bfloat16 g_Enh[(size_t)B_TOT * D_DIM];  // normalized embeddings bf16
__device__ __nv_bfloat16 g_Cnh[(size_t)S_CLS * D_DIM];  // normalized centroids bf16 (x log2e)
__device__ float g_rowsum[B_TOT];                       // sum_k exp(sim[row,k])
__device__ float g_pos[B_TOT];                          // sim[row, label(row)]

// ===========================================================================
// helpers
// ===========================================================================
__device__ __forceinline__ uint32_t smem_to_u32(const void* p) {
    uint32_t a;
    asm("{ .reg .u64 t; cvta.to.shared.u64 t, %1; cvt.u32.u64 %0, t; }"
        : "=r"(a) : "l"(p));
    return a;
}
__device__ __forceinline__ void cp16(uint32_t dst, const void* src) {
    asm volatile("cp.async.cg.shared.global [%0], [%1], 16;"
                 :: "r"(dst), "l"(src) : "memory");
}
__device__ __forceinline__ float warpSum(float v) {
    #pragma unroll
    for (int o = 16; o; o >>= 1) v += __shfl_xor_sync(0xffffffffu, v, o);
    return v;
}
__device__ __forceinline__ float dot4(float4 a, float4 b) {
    return a.x*b.x + a.y*b.y + a.z*b.z + a.w*b.w;
}
__device__ __forceinline__ uint32_t pack_bf16x2(float lo, float hi) {
    __nv_bfloat162 p = __float22bfloat162_rn(make_float2(lo, hi));
    return *reinterpret_cast<uint32_t*>(&p);
}
__device__ __forceinline__ float ex2f(float x) {
    float r;
    asm("ex2.approx.ftz.f32 %0, %1;" : "=f"(r) : "f"(x));
    return r;
}

// ---------------------------------------------------------------------------
// Kernel 1 (pre-pass, warp-per-speaker): grid 256 x 256thr; warp w owns
// speaker s = blockIdx*8 + w; lane owns 8 dims. NO smem, NO __syncthreads.
// Pass 1: centroid accumulated in registers (20 independent LDG.128/lane),
//   normalize, write g_Cnh (x log2e).
// Pass 2: re-read rows (L2-resident: reuse distance = 10KB), per-row sqnorm
//   + pos warpSums, write bf16 g_Enh + g_pos.
// Zeroes this block's 80 rowsum slots and (block 0) out[0].
// ---------------------------------------------------------------------------
__global__ __launch_bounds__(256)
void pre_kernel(const float* __restrict__ emb, float* __restrict__ out) {
    const int w    = threadIdx.x >> 5;
    const int lane = threadIdx.x & 31;
    const int t    = threadIdx.x;
    const int s    = blockIdx.x * 8 + w;
    if (blockIdx.x == 0 && t == 0) out[0] = 0.0f;
    if (t < 80) g_rowsum[blockIdx.x * 80 + t] = 0.0f;

    const float4* base = (const float4*)(emb + (size_t)s * U_UTT * D_DIM);

    // ---- pass 1: centroid in registers ----
    float4 ca = make_float4(0.f, 0.f, 0.f, 0.f);
    float4 cb = ca;
    #pragma unroll
    for (int u = 0; u < U_UTT; u++) {
        float4 x = base[u * 64 + lane];
        float4 y = base[u * 64 + 32 + lane];
        ca.x += x.x; ca.y += x.y; ca.z += x.z; ca.w += x.w;
        cb.x += y.x; cb.y += y.y; cb.z += y.z; cb.w += y.w;
    }
    const float inv = 1.0f / U_UTT;
    ca.x *= inv; ca.y *= inv; ca.z *= inv; ca.w *= inv;
    cb.x *= inv; cb.y *= inv; cb.z *= inv; cb.w *= inv;
    float csq = warpSum(dot4(ca, ca) + dot4(cb, cb));
    float cs = 1.0f / fmaxf(sqrtf(csq), EPSF);
    ca.x *= cs; ca.y *= cs; ca.z *= cs; ca.w *= cs;   // normalized centroid
    cb.x *= cs; cb.y *= cs; cb.z *= cs; cb.w *= cs;
    uint2* ch = (uint2*)(g_Cnh + (size_t)s * D_DIM);
    ch[lane]      = make_uint2(pack_bf16x2(ca.x * LOG2E, ca.y * LOG2E),
                               pack_bf16x2(ca.z * LOG2E, ca.w * LOG2E));
    ch[32 + lane] = make_uint2(pack_bf16x2(cb.x * LOG2E, cb.y * LOG2E),
                               pack_bf16x2(cb.z * LOG2E, cb.w * LOG2E));

    // ---- pass 2: rows (L2-resident re-read) ----
    #pragma unroll
    for (int u = 0; u < U_UTT; u++) {
        float4 x = base[u * 64 + lane];
        float4 y = base[u * 64 + 32 + lane];
        float sq = warpSum(dot4(x, x) + dot4(y, y));
        float pd = warpSum(dot4(x, ca) + dot4(y, cb));
        float sc = 1.0f / fmaxf(sqrtf(sq), EPSF);
        x.x *= sc; x.y *= sc; x.z *= sc; x.w *= sc;
        y.x *= sc; y.y *= sc; y.z *= sc; y.w *= sc;
        const size_t row = (size_t)s * U_UTT + u;
        uint2* eh = (uint2*)(g_Enh + row * D_DIM);
        eh[lane]      = make_uint2(pack_bf16x2(x.x, x.y), pack_bf16x2(x.z, x.w));
        eh[32 + lane] = make_uint2(pack_bf16x2(y.x, y.y), pack_bf16x2(y.z, y.w));
        if (lane == 0) g_pos[row] = pd * sc;
    }
}

// ---------------------------------------------------------------------------
// Kernel 2: bf16 mma.sync GEMM (En @ Cn^T·log2e) 128x128 tile, BK=64,
// cp.async double buffer (proven R12/R15 config, byte-identical).
// Epilogue: bare ex2.approx + quad-reduce + atomicAdd rowsum.
// ---------------------------------------------------------------------------
#define GEMM_SMEM 65536

__global__ __launch_bounds__(256, 2)
void gemm_bf16_kernel() {
    extern __shared__ char smem[];
    const uint32_t sb = smem_to_u32(smem);
    const int tid  = threadIdx.x;
    const int lane = tid & 31;
    const int wid  = tid >> 5;
    const int rowTile = blockIdx.x * 128;
    const int colTile = blockIdx.y * 128;
    const int rowBase = (wid >> 2) * 64;   // warp row  (0 or 64)
    const int colBase = (wid & 3) * 32;    // warp col  (0,32,64,96)

    const int lrow = tid >> 3;   // 0..31 ; rows lrow + 32*j
    const int lseg = tid & 7;    // 16B segment within 128B row

    float acc[4][4][4];
    #pragma unroll
    for (int mi = 0; mi < 4; mi++)
        #pragma unroll
        for (int ni = 0; ni < 4; ni++)
            #pragma unroll
            for (int q = 0; q < 4; q++) acc[mi][ni][q] = 0.0f;

    auto load_chunk = [&](int c, int buf) {
        #pragma unroll
        for (int j = 0; j < 4; j++) {
            int row = lrow + 32 * j;
            uint32_t dst = sb + buf * 32768 + row * 128
                         + ((lseg * 16) ^ ((row & 7) << 4));
            cp16(dst,
                 g_Enh + (size_t)(rowTile + row) * D_DIM + c * 64 + lseg * 8);
            cp16(dst + 16384,
                 g_Cnh + (size_t)(colTile + row) * D_DIM + c * 64 + lseg * 8);
        }
        asm volatile("cp.async.commit_group;" ::: "memory");
    };

    load_chunk(0, 0);
    load_chunk(1, 1);

    #pragma unroll
    for (int c = 0; c < 4; c++) {
        const int buf = c & 1;
        if (c < 3) asm volatile("cp.async.wait_group 1;" ::: "memory");
        else       asm volatile("cp.async.wait_group 0;" ::: "memory");
        __syncthreads();

        const uint32_t aB = sb + buf * 32768;
        const uint32_t bB = aB + 16384;

        #pragma unroll
        for (int ks = 0; ks < 4; ks++) {
            uint32_t a[4][4];
            uint32_t b[4][2];
            #pragma unroll
            for (int mi = 0; mi < 4; mi++) {
                int r = rowBase + mi * 16 + (lane & 15);
                uint32_t addr = aB + r * 128
                    + ((ks * 32 + (lane >> 4) * 16) ^ ((r & 7) << 4));
                asm volatile(
                    "ldmatrix.sync.aligned.m8n8.x4.shared.b16 {%0,%1,%2,%3}, [%4];"
                    : "=r"(a[mi][0]), "=r"(a[mi][1]), "=r"(a[mi][2]), "=r"(a[mi][3])
                    : "r"(addr));
            }
            #pragma unroll
            for (int nn = 0; nn < 2; nn++) {
                int g = lane >> 3;                 // matrix index 0..3
                int r = colBase + (nn * 2 + (g >> 1)) * 8 + (lane & 7);
                uint32_t addr = bB + r * 128
                    + ((ks * 32 + (g & 1) * 16) ^ ((r & 7) << 4));
                asm volatile(
                    "ldmatrix.sync.aligned.m8n8.x4.shared.b16 {%0,%1,%2,%3}, [%4];"
                    : "=r"(b[nn*2][0]), "=r"(b[nn*2][1]),
                      "=r"(b[nn*2+1][0]), "=r"(b[nn*2+1][1])
                    : "r"(addr));
            }
            #pragma unroll
            for (int mi = 0; mi < 4; mi++)
                #pragma unroll
                for (int ni = 0; ni < 4; ni++) {
                    asm volatile(
                        "mma.sync.aligned.m16n8k16.row.col.f32.bf16.bf16.f32 "
                        "{%0,%1,%2,%3}, {%4,%5,%6,%7}, {%8,%9}, {%0,%1,%2,%3};"
                        : "+f"(acc[mi][ni][0]), "+f"(acc[mi][ni][1]),
                          "+f"(acc[mi][ni][2]), "+f"(acc[mi][ni][3])
                        : "r"(a[mi][0]), "r"(a[mi][1]), "r"(a[mi][2]), "r"(a[mi][3]),
                          "r"(b[ni][0]), "r"(b[ni][1]));
                }
        }
        __syncthreads();
        if (c + 2 < 4) load_chunk(c + 2, buf);
    }

    // epilogue: acc holds sim*log2e -> bare ex2 + quad-reduce + atomicAdd
    const int g  = lane >> 2;
    const int tg = lane & 3;
    #pragma unroll
    for (int mi = 0; mi < 4; mi++) {
        float s0 = 0.0f, s1 = 0.0f;
        #pragma unroll
        for (int ni = 0; ni < 4; ni++) {
            s0 += ex2f(acc[mi][ni][0]) + ex2f(acc[mi][ni][1]);
            s1 += ex2f(acc[mi][ni][2]) + ex2f(acc[mi][ni][3]);
        }
        s0 += __shfl_xor_sync(0xffffffffu, s0, 1);
        s0 += __shfl_xor_sync(0xffffffffu, s0, 2);
        s1 += __shfl_xor_sync(0xffffffffu, s1, 1);
        s1 += __shfl_xor_sync(0xffffffffu, s1, 2);
        if (tg == 0) {
            int r = rowTile + rowBase + mi * 16 + g;
            atomicAdd(&g_rowsum[r],     s0);
            atomicAdd(&g_rowsum[r + 8], s1);
        }
    }
}

// ---------------------------------------------------------------------------
// Kernel 3: loss partials -> atomicAdd into out[0] (zeroed by pre_kernel).
// ---------------------------------------------------------------------------
__global__ void loss_kernel(float* __restrict__ out) {
    int i = blockIdx.x * 256 + threadIdx.x;
    float p = g_pos[i];
    float acc = __logf(g_rowsum[i] - __expf(p)) - p;
    __shared__ float sh[8];
    int lane = threadIdx.x & 31, w = threadIdx.x >> 5;
    acc = warpSum(acc);
    if (lane == 0) sh[w] = acc;
    __syncthreads();
    if (w == 0) {
        acc = (lane < 8) ? sh[lane] : 0.0f;
        #pragma unroll
        for (int o = 4; o; o >>= 1) acc += __shfl_xor_sync(0xffffffffu, acc, o);
        if (lane == 0) atomicAdd(out, acc * (1.0f / B_TOT));
    }
}

// ---------------------------------------------------------------------------
extern "C" void kernel_launch(void* const* d_in, const int* in_sizes, int n_in,
                              void* d_out, int out_size) {
    const float* emb = (const float*)d_in[0];
    float* out = (float*)d_out;

    cudaFuncSetAttribute(gemm_bf16_kernel,
                         cudaFuncAttributeMaxDynamicSharedMemorySize,
                         GEMM_SMEM);

    pre_kernel<<<S_CLS / 8, 256>>>(emb, out);
    dim3 grid(B_TOT / 128, S_CLS / 128);
    gemm_bf16_kernel<<<grid, 256, GEMM_SMEM>>>();
    loss_kernel<<<B_TOT / 256, 256>>>(out);
}